// round 10
// baseline (speedup 1.0000x reference)
#include <cuda_runtime.h>
#include <math_constants.h>
#include <cstdint>

// ===========================================================================
// CasualAttention via tf32 mma.sync (m16n8k8), fragment-packed operands,
// register double-buffered fragment pipeline.
//   x[4,2048,1024] fp32, W*[1024,1024] fp32 -> out[4,2048,1024] fp32
// All GEMMs NT: D[m,n] = sum_k A[m,k]*B[n,k].
// A packed: [mblk=M/16][kblk=K/8][lane32][reg4] (512B blocks)
// B packed: [nblk=N/8][kblk=K/8][lane32][reg2] (256B blocks)
// 256 thr/CTA, 8 warps (2x4), warp tile 64x32.
// ===========================================================================

#define BATCH 4
#define SEQ   2048
#define DIM   1024
#define MROWS (BATCH * SEQ)

#define BM 128
#define BN 128
#define BK 32
#define NSTAGES 3
#define STAGE_F 8192                      // floats: A 4096 + B 4096
#define SMEM_BYTES (NSTAGES * STAGE_F * 4)   // 98304

// ---------------- scratch ---------------------------------------------------
__device__ float g_PAX[512 * 128 * 128];              // x packed-A   (32MB)
__device__ float g_PBW[3 * 128 * 128 * 64];           // W^T packed-B (12MB)
__device__ float g_PAQ[(size_t)BATCH * 128 * 128 * 128];   // Q packed-A
__device__ float g_PBK[(size_t)BATCH * 256 * 128 * 64];    // K packed-B
__device__ float g_PBV[(size_t)BATCH * 128 * 256 * 64];    // V^T packed-B
__device__ float g_PAS[(size_t)BATCH * 128 * 256 * 128];   // S/P packed-A (64MB)

// ---------------- helpers ---------------------------------------------------
__device__ __forceinline__ uint32_t smem_u32(const void* p) {
    uint32_t a;
    asm("{ .reg .u64 t; cvta.to.shared.u64 t, %1; cvt.u32.u64 %0, t; }"
        : "=r"(a) : "l"(p));
    return a;
}
__device__ __forceinline__ float rna_tf32(float x) {
    float r;
    asm("cvt.rna.tf32.f32 %0, %1;" : "=f"(r) : "f"(x));
    return r;
}
__device__ __forceinline__ void cp16(float* dst, const float* src) {
    uint32_t d = smem_u32(dst);
    asm volatile("cp.async.cg.shared.global [%0], [%1], 16;" :: "r"(d), "l"(src));
}
#define CP_COMMIT() asm volatile("cp.async.commit_group;" ::: "memory")
#define CP_WAIT1()  asm volatile("cp.async.wait_group 1;"  ::: "memory")

__device__ __forceinline__ void mma8(float d[4], float4 a, float2 b) {
    asm volatile(
        "mma.sync.aligned.m16n8k8.row.col.f32.tf32.tf32.f32 "
        "{%0,%1,%2,%3}, {%4,%5,%6,%7}, {%8,%9}, {%0,%1,%2,%3};"
        : "+f"(d[0]), "+f"(d[1]), "+f"(d[2]), "+f"(d[3])
        : "r"(__float_as_uint(a.x)), "r"(__float_as_uint(a.y)),
          "r"(__float_as_uint(a.z)), "r"(__float_as_uint(a.w)),
          "r"(__float_as_uint(b.x)), "r"(__float_as_uint(b.y)));
}

// packed-A float index within one matrix (kbTot = K/8)
__device__ __forceinline__ size_t paIdx(int kbTot, int r, int c) {
    return (((size_t)(r >> 4) * kbTot + (c >> 3)) << 7)
         + (((r & 7) << 2) + (c & 3)) * 4 + ((r >> 3) & 1) + (((c >> 2) & 1) << 1);
}
// packed-B float index (kbTot = K/8)
__device__ __forceinline__ size_t pbIdx(int kbTot, int n, int k) {
    return (((size_t)(n >> 3) * kbTot + (k >> 3)) << 6)
         + (((n & 7) << 2) + (k & 3)) * 2 + ((k >> 2) & 1);
}

// ---------------- GEMM mainloop ---------------------------------------------
// 256 threads = 8 warps (2x4); warp tile 64x32.
__device__ __forceinline__ void load_stage(float* st,
                                           const float* __restrict__ Ab, int ka,
                                           const float* __restrict__ Bb, int kbt,
                                           int kb0)
{
    const int t = threadIdx.x;
    #pragma unroll
    for (int j = 0; j < 4; j++) {          // A: 1024 float4
        int f = t + j * 256;
        int mb = f >> 7, r = f & 127, kb = r >> 5, li = r & 31;
        cp16(st + mb * 512 + kb * 128 + li * 4,
             Ab + ((size_t)mb * ka + kb0 + kb) * 128 + li * 4);
    }
    #pragma unroll
    for (int j = 0; j < 4; j++) {          // B: 1024 float4
        int f = t + j * 256;
        int nb = f >> 6, r = f & 63, kb = r >> 4, li = r & 15;
        cp16(st + 4096 + nb * 256 + kb * 64 + li * 4,
             Bb + ((size_t)nb * kbt + kb0 + kb) * 64 + li * 4);
    }
}

__device__ __forceinline__ void ldfrag(const float* sA, const float* sB,
                                       int ks, int lane, float4 a[4], float2 b[4])
{
    #pragma unroll
    for (int mf = 0; mf < 4; mf++)
        a[mf] = *reinterpret_cast<const float4*>(sA + mf * 512 + ks * 128 + lane * 4);
    #pragma unroll
    for (int nf = 0; nf < 4; nf++)
        b[nf] = *reinterpret_cast<const float2*>(sB + nf * 256 + ks * 64 + lane * 2);
}

__device__ __forceinline__ void mmaslice(float acc[4][4][4], const float4 a[4], const float2 b[4])
{
    #pragma unroll
    for (int mf = 0; mf < 4; mf++)
        #pragma unroll
        for (int nf = 0; nf < 4; nf++)
            mma8(acc[mf][nf], a[mf], b[nf]);
}

__device__ __forceinline__ void gemm_main(const float* __restrict__ Ab, int ka,
                                          const float* __restrict__ Bb, int kbt,
                                          int kIters, float acc[4][4][4])
{
    extern __shared__ float smem[];
    const int wid  = threadIdx.x >> 5;
    const int lane = threadIdx.x & 31;

    #pragma unroll
    for (int s = 0; s < NSTAGES - 1; s++) {
        load_stage(smem + s * STAGE_F, Ab, ka, Bb, kbt, s * 4);
        CP_COMMIT();
    }

    int slot = 0;
    for (int it = 0; it < kIters; it++) {
        CP_WAIT1();
        __syncthreads();

        const int nk = it + NSTAGES - 1;
        if (nk < kIters) {
            int ns = nk % NSTAGES;
            load_stage(smem + ns * STAGE_F, Ab, ka, Bb, kbt, nk * 4);
        }
        CP_COMMIT();

        const float* sA = smem + slot * STAGE_F + ((wid >> 2) * 4) * 512;
        const float* sB = smem + slot * STAGE_F + 4096 + ((wid & 3) * 4) * 256;

        // register double-buffered fragment pipeline over the 4 k-slices
        float4 a0[4], a1[4];
        float2 b0[4], b1[4];
        ldfrag(sA, sB, 0, lane, a0, b0);
        ldfrag(sA, sB, 1, lane, a1, b1);
        mmaslice(acc, a0, b0);
        ldfrag(sA, sB, 2, lane, a0, b0);
        mmaslice(acc, a1, b1);
        ldfrag(sA, sB, 3, lane, a1, b1);
        mmaslice(acc, a0, b0);
        mmaslice(acc, a1, b1);

        if (++slot == NSTAGES) slot = 0;
    }
}

#define ZERO_ACC(acc) do { \
    _Pragma("unroll") for (int _i = 0; _i < 4; _i++) \
    _Pragma("unroll") for (int _j = 0; _j < 4; _j++) \
    _Pragma("unroll") for (int _l = 0; _l < 4; _l++) acc[_i][_j][_l] = 0.0f; \
} while (0)

// epilogue coordinates: warp (wid>>2) m-half, (wid&3) n-quarter
#define EPI_COORDS() \
    const int wid = threadIdx.x >> 5, lane = threadIdx.x & 31; \
    const int g = lane >> 2, tg = lane & 3; \
    const int rb = ((wid >> 2) << 6) + g; \
    const int cb = ((wid & 3) << 5) + 2 * tg

// ---------------- GEMM kernels ----------------------------------------------
__global__ __launch_bounds__(256, 2)
void proj_kernel()
{
    const int z  = blockIdx.z;
    const int m0 = blockIdx.y * BM;          // global row 0..8191
    const int n0 = blockIdx.x * BN;          // 0..1023
    const float* Ab = g_PAX + ((size_t)(m0 >> 4) * 128) * 128;
    const float* Bb = g_PBW + ((size_t)(z * 128 + (n0 >> 3)) * 128) * 64;

    float acc[4][4][4];
    ZERO_ACC(acc);
    gemm_main(Ab, 128, Bb, 128, DIM / BK, acc);

    EPI_COORDS();
    const int b = m0 >> 11;
    const int rbg = m0 + rb, cbg = n0 + cb;

    if (z == 0) {
        float* base = g_PAQ + (size_t)b * (128 * 128 * 128);
        #pragma unroll
        for (int mf = 0; mf < 4; mf++)
            #pragma unroll
            for (int nf = 0; nf < 4; nf++) {
                const int r = (rbg + mf * 16) & 2047, c = cbg + nf * 8;
                base[paIdx(128, r,     c    )] = rna_tf32(acc[mf][nf][0]);
                base[paIdx(128, r,     c + 1)] = rna_tf32(acc[mf][nf][1]);
                base[paIdx(128, r + 8, c    )] = rna_tf32(acc[mf][nf][2]);
                base[paIdx(128, r + 8, c + 1)] = rna_tf32(acc[mf][nf][3]);
            }
    } else if (z == 1) {
        float* base = g_PBK + (size_t)b * (256 * 128 * 64);
        #pragma unroll
        for (int mf = 0; mf < 4; mf++)
            #pragma unroll
            for (int nf = 0; nf < 4; nf++) {
                const int r = (rbg + mf * 16) & 2047, c = cbg + nf * 8;
                base[pbIdx(128, r,     c    )] = rna_tf32(acc[mf][nf][0]);
                base[pbIdx(128, r,     c + 1)] = rna_tf32(acc[mf][nf][1]);
                base[pbIdx(128, r + 8, c    )] = rna_tf32(acc[mf][nf][2]);
                base[pbIdx(128, r + 8, c + 1)] = rna_tf32(acc[mf][nf][3]);
            }
    } else {
        // V: write directly in packed-B(V^T) layout: n=dim col, k=seq row
        float* base = g_PBV + (size_t)b * (128 * 256 * 64);
        #pragma unroll
        for (int mf = 0; mf < 4; mf++)
            #pragma unroll
            for (int nf = 0; nf < 4; nf++) {
                const int r = (rbg + mf * 16) & 2047, c = cbg + nf * 8;
                base[pbIdx(256, c,     r    )] = rna_tf32(acc[mf][nf][0]);
                base[pbIdx(256, c + 1, r    )] = rna_tf32(acc[mf][nf][1]);
                base[pbIdx(256, c,     r + 8)] = rna_tf32(acc[mf][nf][2]);
                base[pbIdx(256, c + 1, r + 8)] = rna_tf32(acc[mf][nf][3]);
            }
    }
}

__global__ __launch_bounds__(256, 2)
void qk_kernel()
{
    // compact triangular grid: blockIdx.x in [0,136)
    const int b = blockIdx.y;
    const int i = blockIdx.x;
    int qt = (int)((sqrtf(8.0f * i + 1.0f) - 1.0f) * 0.5f);
    while ((qt + 1) * (qt + 2) / 2 <= i) qt++;
    while (qt * (qt + 1) / 2 > i) qt--;
    const int kt = i - qt * (qt + 1) / 2;
    const int q0 = qt * BM;
    const int k0 = kt * BN;

    const float* Ab = g_PAQ + (size_t)b * (128*128*128) + ((size_t)(q0 >> 4) * 128) * 128;
    const float* Bb = g_PBK + (size_t)b * (256*128*64)  + ((size_t)(k0 >> 3) * 128) * 64;

    float acc[4][4][4];
    ZERO_ACC(acc);
    gemm_main(Ab, 128, Bb, 128, DIM / BK, acc);

    float* base = g_PAS + (size_t)b * (128 * 256 * 128);
    const float scale = 0.03125f;
    EPI_COORDS();
    const int rbg = q0 + rb, cbg = k0 + cb;
    #pragma unroll
    for (int mf = 0; mf < 4; mf++)
        #pragma unroll
        for (int nf = 0; nf < 4; nf++) {
            const int r0 = rbg + mf * 16, r1 = r0 + 8;
            const int c  = cbg + nf * 8;
            base[paIdx(256, r0, c    )] = (c     <= r0) ? acc[mf][nf][0] * scale : -CUDART_INF_F;
            base[paIdx(256, r0, c + 1)] = (c + 1 <= r0) ? acc[mf][nf][1] * scale : -CUDART_INF_F;
            base[paIdx(256, r1, c    )] = (c     <= r1) ? acc[mf][nf][2] * scale : -CUDART_INF_F;
            base[paIdx(256, r1, c + 1)] = (c + 1 <= r1) ? acc[mf][nf][3] * scale : -CUDART_INF_F;
        }
}

__global__ __launch_bounds__(256, 2)
void pv_kernel(float* __restrict__ out)
{
    const int b  = blockIdx.z;
    const int q0 = (SEQ / BM - 1 - blockIdx.y) * BM;   // heavy tiles first
    const int n0 = blockIdx.x * BN;

    const float* Ab = g_PAS + (size_t)b * (128*256*128) + ((size_t)(q0 >> 4) * 256) * 128;
    const float* Bb = g_PBV + (size_t)b * (128*256*64)  + ((size_t)(n0 >> 3) * 256) * 64;

    float acc[4][4][4];
    ZERO_ACC(acc);
    gemm_main(Ab, 256, Bb, 256, (q0 + BM) / BK, acc);

    float* O = out + (size_t)b * SEQ * DIM;
    EPI_COORDS();
    const int rbg = q0 + rb, cbg = n0 + cb;
    #pragma unroll
    for (int mf = 0; mf < 4; mf++)
        #pragma unroll
        for (int nf = 0; nf < 4; nf++) {
            float* p0 = O + (size_t)(rbg + mf * 16) * DIM + cbg + nf * 8;
            float* p1 = O + (size_t)(rbg + mf * 16 + 8) * DIM + cbg + nf * 8;
            *reinterpret_cast<float2*>(p0) = make_float2(acc[mf][nf][0], acc[mf][nf][1]);
            *reinterpret_cast<float2*>(p1) = make_float2(acc[mf][nf][2], acc[mf][nf][3]);
        }
}

// ---------------- pack kernels ----------------------------------------------
__global__ __launch_bounds__(256)
void pack_x_kernel(const float* __restrict__ x)
{
    __shared__ float sm[16][260];
    const int mb = blockIdx.x;              // 0..511 (16-row group of 8192)
    const int kc = blockIdx.y;              // 0..3 (256-col chunk)
    const float* src = x + (size_t)mb * 16 * DIM + kc * 256;
    for (int i = threadIdx.x; i < 1024; i += 256) {   // 16x256 floats as float4
        int row = i >> 6, c4 = i & 63;
        float4 v = *reinterpret_cast<const float4*>(src + (size_t)row * DIM + c4 * 4);
        *reinterpret_cast<float4*>(&sm[row][c4 * 4]) = v;
    }
    __syncthreads();
    #pragma unroll
    for (int j = 0; j < 4; j++) {
        int s = threadIdx.x + j * 256;      // 0..1023 = 32 kblk x 32 lanes
        int kbl = s >> 5, L = s & 31;
        int r8 = L >> 2, c4 = L & 3;
        float4 v;
        v.x = rna_tf32(sm[r8    ][kbl * 8 + c4    ]);
        v.y = rna_tf32(sm[r8 + 8][kbl * 8 + c4    ]);
        v.z = rna_tf32(sm[r8    ][kbl * 8 + c4 + 4]);
        v.w = rna_tf32(sm[r8 + 8][kbl * 8 + c4 + 4]);
        *reinterpret_cast<float4*>(
            g_PAX + ((size_t)(mb * 128 + kc * 32 + kbl)) * 128 + L * 4) = v;
    }
}

__global__ __launch_bounds__(256)
void pack_w_kernel(const float* __restrict__ Wq,
                   const float* __restrict__ Wk,
                   const float* __restrict__ Wv)
{
    int s = blockIdx.x * 256 + threadIdx.x;
    int L = s & 31, kblk = (s >> 5) & 127, nblk = (s >> 12) & 127, z = s >> 19;
    const float* W = (z == 0) ? Wq : (z == 1) ? Wk : Wv;
    int n = nblk * 8 + (L >> 2), k = kblk * 8 + (L & 3);
    float2 v;
    v.x = rna_tf32(W[(size_t)k * DIM + n]);
    v.y = rna_tf32(W[(size_t)(k + 4) * DIM + n]);
    *reinterpret_cast<float2*>(
        g_PBW + ((size_t)((z * 128 + nblk) * 128 + kblk)) * 64 + L * 2) = v;
}

// ---------------- softmax on packed layout ----------------------------------
__global__ __launch_bounds__(256)
void softmax_kernel()
{
    const int mblk = blockIdx.x;            // 0..127
    const int b    = blockIdx.y;
    float* base = g_PAS + (size_t)b * (128 * 256 * 128) + (size_t)mblk * 256 * 128;
    const int KB = 2 * mblk + 2;                     // blocks holding k <= m0+15
    const int ZB = ((mblk >> 3) << 4) + 16;          // causal boundary blocks

    const int t = threadIdx.x, kp = t >> 5, lane = t & 31;
    const int r0 = lane >> 2;
    __shared__ float red[16][33];
    __shared__ float rowmax[16], rowinv[16];

    float mlo = -CUDART_INF_F, mhi = -CUDART_INF_F;
    for (int kb = kp; kb < KB; kb += 8) {
        float4 f = *reinterpret_cast<const float4*>(base + kb * 128 + lane * 4);
        mlo = fmaxf(mlo, fmaxf(f.x, f.z));
        mhi = fmaxf(mhi, fmaxf(f.y, f.w));
    }
    red[r0][kp * 4 + (lane & 3)] = mlo;
    red[r0 + 8][kp * 4 + (lane & 3)] = mhi;
    __syncthreads();
    if (t < 16) {
        float m = -CUDART_INF_F;
        #pragma unroll
        for (int j = 0; j < 32; j++) m = fmaxf(m, red[t][j]);
        rowmax[t] = m;
    }
    __syncthreads();
    const float Mlo = rowmax[r0], Mhi = rowmax[r0 + 8];

    float slo = 0.0f, shi = 0.0f;
    for (int kb = kp; kb < KB; kb += 8) {
        float4 f = *reinterpret_cast<const float4*>(base + kb * 128 + lane * 4);
        slo += __expf(f.x - Mlo) + __expf(f.z - Mlo);
        shi += __expf(f.y - Mhi) + __expf(f.w - Mhi);
    }
    __syncthreads();
    red[r0][kp * 4 + (lane & 3)] = slo;
    red[r0 + 8][kp * 4 + (lane & 3)] = shi;
    __syncthreads();
    if (t < 16) {
        float ssum = 0.0f;
        #pragma unroll
        for (int j = 0; j < 32; j++) ssum += red[t][j];
        rowinv[t] = 1.0f / ssum;
    }
    __syncthreads();
    const float Ilo = rowinv[r0], Ihi = rowinv[r0 + 8];

    for (int kb = kp; kb < KB; kb += 8) {
        float4 f = *reinterpret_cast<float4*>(base + kb * 128 + lane * 4);
        f.x = rna_tf32(__expf(f.x - Mlo) * Ilo);
        f.z = rna_tf32(__expf(f.z - Mlo) * Ilo);
        f.y = rna_tf32(__expf(f.y - Mhi) * Ihi);
        f.w = rna_tf32(__expf(f.w - Mhi) * Ihi);
        *reinterpret_cast<float4*>(base + kb * 128 + lane * 4) = f;
    }

    // zero the masked blocks [KB, ZB) (read dense by PV)
    const int nz4 = (ZB - KB) * 32;
    float4 z4 = make_float4(0.f, 0.f, 0.f, 0.f);
    for (int i = t; i < nz4; i += 256)
        reinterpret_cast<float4*>(base + KB * 128)[i] = z4;
}

// ---------------- host side --------------------------------------------------
extern "C" void kernel_launch(void* const* d_in, const int* in_sizes, int n_in,
                              void* d_out, int out_size)
{
    const float* x  = (const float*)d_in[0];
    const float* Wq = (const float*)d_in[1];
    const float* Wk = (const float*)d_in[2];
    const float* Wv = (const float*)d_in[3];
    float* out = (float*)d_out;

    static bool configured = false;
    if (!configured) {
        cudaFuncSetAttribute(proj_kernel, cudaFuncAttributeMaxDynamicSharedMemorySize, SMEM_BYTES);
        cudaFuncSetAttribute(qk_kernel,   cudaFuncAttributeMaxDynamicSharedMemorySize, SMEM_BYTES);
        cudaFuncSetAttribute(pv_kernel,   cudaFuncAttributeMaxDynamicSharedMemorySize, SMEM_BYTES);
        configured = true;
    }

    pack_x_kernel<<<dim3(512, 4), 256>>>(x);
    pack_w_kernel<<<6144, 256>>>(Wq, Wk, Wv);
    proj_kernel<<<dim3(DIM / BN, MROWS / BM, 3), 256, SMEM_BYTES>>>();
    qk_kernel<<<dim3(136, BATCH), 256, SMEM_BYTES>>>();   // profiled idx 3, compact grid
    softmax_kernel<<<dim3(128, BATCH), 256>>>();
    pv_kernel<<<dim3(DIM / BN, SEQ / BM, BATCH), 256, SMEM_BYTES>>>(out);
}

// round 12
// speedup vs baseline: 1.0890x; 1.0890x over previous
#include <cuda_runtime.h>
#include <math_constants.h>
#include <cstdint>

// ===========================================================================
// CasualAttention via tf32 mma.sync (m16n8k8), fragment-packed operands.
//   x[4,2048,1024] fp32, W*[1024,1024] fp32 -> out[4,2048,1024] fp32
// All GEMMs NT: D[m,n] = sum_k A[m,k]*B[n,k].
// A packed: [mblk=M/16][kblk=K/8][lane32][reg4] (512B blocks)
// B packed: [nblk=N/8][kblk=K/8][lane32][reg2] (256B blocks)
// 128 thr/CTA, 4 warps (2x2), warp tile 64x64 (measured-best mainloop).
// Launches: pack_x, pack_w, proj01 (Q,K), fused(qk + projV), softmax, pv.
// ===========================================================================

#define BATCH 4
#define SEQ   2048
#define DIM   1024
#define MROWS (BATCH * SEQ)

#define BM 128
#define BN 128
#define BK 32
#define NSTAGES 3
#define STAGE_F 8192                      // floats: A 4096 + B 4096
#define SMEM_BYTES (NSTAGES * STAGE_F * 4)   // 98304

// ---------------- scratch ---------------------------------------------------
__device__ float g_PAX[512 * 128 * 128];              // x packed-A   (32MB)
__device__ float g_PBW[3 * 128 * 128 * 64];           // W^T packed-B (12MB)
__device__ float g_PAQ[(size_t)BATCH * 128 * 128 * 128];   // Q packed-A
__device__ float g_PBK[(size_t)BATCH * 256 * 128 * 64];    // K packed-B
__device__ float g_PBV[(size_t)BATCH * 128 * 256 * 64];    // V^T packed-B
__device__ float g_PAS[(size_t)BATCH * 128 * 256 * 128];   // S/P packed-A (64MB)

// ---------------- helpers ---------------------------------------------------
__device__ __forceinline__ uint32_t smem_u32(const void* p) {
    uint32_t a;
    asm("{ .reg .u64 t; cvta.to.shared.u64 t, %1; cvt.u32.u64 %0, t; }"
        : "=r"(a) : "l"(p));
    return a;
}
__device__ __forceinline__ float rna_tf32(float x) {
    float r;
    asm("cvt.rna.tf32.f32 %0, %1;" : "=f"(r) : "f"(x));
    return r;
}
__device__ __forceinline__ void cp16(float* dst, const float* src) {
    uint32_t d = smem_u32(dst);
    asm volatile("cp.async.cg.shared.global [%0], [%1], 16;" :: "r"(d), "l"(src));
}
#define CP_COMMIT() asm volatile("cp.async.commit_group;" ::: "memory")
#define CP_WAIT1()  asm volatile("cp.async.wait_group 1;"  ::: "memory")

__device__ __forceinline__ void mma8(float d[4], float4 a, float2 b) {
    asm volatile(
        "mma.sync.aligned.m16n8k8.row.col.f32.tf32.tf32.f32 "
        "{%0,%1,%2,%3}, {%4,%5,%6,%7}, {%8,%9}, {%0,%1,%2,%3};"
        : "+f"(d[0]), "+f"(d[1]), "+f"(d[2]), "+f"(d[3])
        : "r"(__float_as_uint(a.x)), "r"(__float_as_uint(a.y)),
          "r"(__float_as_uint(a.z)), "r"(__float_as_uint(a.w)),
          "r"(__float_as_uint(b.x)), "r"(__float_as_uint(b.y)));
}

// packed-A float index within one matrix (kbTot = K/8)
__device__ __forceinline__ size_t paIdx(int kbTot, int r, int c) {
    return (((size_t)(r >> 4) * kbTot + (c >> 3)) << 7)
         + (((r & 7) << 2) + (c & 3)) * 4 + ((r >> 3) & 1) + (((c >> 2) & 1) << 1);
}
// packed-B float index (kbTot = K/8)
__device__ __forceinline__ size_t pbIdx(int kbTot, int n, int k) {
    return (((size_t)(n >> 3) * kbTot + (k >> 3)) << 6)
         + (((n & 7) << 2) + (k & 3)) * 2 + ((k >> 2) & 1);
}

// ---------------- GEMM mainloop (round-8 measured-best shape) ----------------
// 128 threads = 4 warps (2x2); warp tile 64x64.
__device__ __forceinline__ void load_stage(float* st,
                                           const float* __restrict__ Ab, int ka,
                                           const float* __restrict__ Bb, int kbt,
                                           int kb0)
{
    const int t = threadIdx.x;
    {
        const int mb = t >> 4, c0 = t & 15;
        const float* src = Ab + ((size_t)mb * ka + kb0) * 128;
        float* dst = st + mb * 512;
        #pragma unroll
        for (int j = 0; j < 8; j++)
            cp16(dst + (c0 + 16 * j) * 4, src + (c0 + 16 * j) * 4);
    }
    {
        const int nb = t >> 3, c0 = t & 7;
        const float* src = Bb + ((size_t)nb * kbt + kb0) * 64;
        float* dst = st + 4096 + nb * 256;
        #pragma unroll
        for (int j = 0; j < 8; j++)
            cp16(dst + (c0 + 8 * j) * 4, src + (c0 + 8 * j) * 4);
    }
}

__device__ __forceinline__ void gemm_main(const float* __restrict__ Ab, int ka,
                                          const float* __restrict__ Bb, int kbt,
                                          int kIters, float acc[4][8][4])
{
    extern __shared__ float smem[];
    const int wid  = threadIdx.x >> 5;
    const int lane = threadIdx.x & 31;

    #pragma unroll
    for (int s = 0; s < NSTAGES - 1; s++) {
        load_stage(smem + s * STAGE_F, Ab, ka, Bb, kbt, s * 4);
        CP_COMMIT();
    }

    int slot = 0;
    for (int it = 0; it < kIters; it++) {
        CP_WAIT1();
        __syncthreads();

        const int nk = it + NSTAGES - 1;
        if (nk < kIters) {
            int ns = nk % NSTAGES;
            load_stage(smem + ns * STAGE_F, Ab, ka, Bb, kbt, nk * 4);
        }
        CP_COMMIT();

        const float* sA = smem + slot * STAGE_F + ((wid >> 1) * 4) * 512;
        const float* sB = smem + slot * STAGE_F + 4096 + ((wid & 1) * 8) * 256;

        #pragma unroll
        for (int ks = 0; ks < 4; ks++) {
            float4 av[4];
            #pragma unroll
            for (int mf = 0; mf < 4; mf++)
                av[mf] = *reinterpret_cast<const float4*>(sA + mf * 512 + ks * 128 + lane * 4);
            float2 bv[8];
            #pragma unroll
            for (int nf = 0; nf < 8; nf++)
                bv[nf] = *reinterpret_cast<const float2*>(sB + nf * 256 + ks * 64 + lane * 2);
            #pragma unroll
            for (int mf = 0; mf < 4; mf++)
                #pragma unroll
                for (int nf = 0; nf < 8; nf++)
                    mma8(acc[mf][nf], av[mf], bv[nf]);
        }
        if (++slot == NSTAGES) slot = 0;
    }
}

#define ZERO_ACC(acc) do { \
    _Pragma("unroll") for (int _i = 0; _i < 4; _i++) \
    _Pragma("unroll") for (int _j = 0; _j < 8; _j++) \
    _Pragma("unroll") for (int _l = 0; _l < 4; _l++) acc[_i][_j][_l] = 0.0f; \
} while (0)

// epilogue coordinates (4-warp 2x2, warp tile 64x64)
#define EPI_COORDS() \
    const int wid = threadIdx.x >> 5, lane = threadIdx.x & 31; \
    const int g = lane >> 2, tg = lane & 3; \
    const int rb = ((wid >> 1) << 6) + g; \
    const int cb = ((wid & 1) << 6) + 2 * tg

// ---------------- role bodies ------------------------------------------------
__device__ __forceinline__ void do_proj(int z, int m0, int n0)
{
    const float* Ab = g_PAX + ((size_t)(m0 >> 4) * 128) * 128;
    const float* Bb = g_PBW + ((size_t)(z * 128 + (n0 >> 3)) * 128) * 64;

    float acc[4][8][4];
    ZERO_ACC(acc);
    gemm_main(Ab, 128, Bb, 128, DIM / BK, acc);

    EPI_COORDS();
    const int b = m0 >> 11;
    const int rbg = m0 + rb, cbg = n0 + cb;

    if (z == 0) {
        float* base = g_PAQ + (size_t)b * (128 * 128 * 128);
        #pragma unroll
        for (int mf = 0; mf < 4; mf++)
            #pragma unroll
            for (int nf = 0; nf < 8; nf++) {
                const int r = (rbg + mf * 16) & 2047, c = cbg + nf * 8;
                base[paIdx(128, r,     c    )] = rna_tf32(acc[mf][nf][0]);
                base[paIdx(128, r,     c + 1)] = rna_tf32(acc[mf][nf][1]);
                base[paIdx(128, r + 8, c    )] = rna_tf32(acc[mf][nf][2]);
                base[paIdx(128, r + 8, c + 1)] = rna_tf32(acc[mf][nf][3]);
            }
    } else if (z == 1) {
        float* base = g_PBK + (size_t)b * (256 * 128 * 64);
        #pragma unroll
        for (int mf = 0; mf < 4; mf++)
            #pragma unroll
            for (int nf = 0; nf < 8; nf++) {
                const int r = (rbg + mf * 16) & 2047, c = cbg + nf * 8;
                base[pbIdx(128, r,     c    )] = rna_tf32(acc[mf][nf][0]);
                base[pbIdx(128, r,     c + 1)] = rna_tf32(acc[mf][nf][1]);
                base[pbIdx(128, r + 8, c    )] = rna_tf32(acc[mf][nf][2]);
                base[pbIdx(128, r + 8, c + 1)] = rna_tf32(acc[mf][nf][3]);
            }
    } else {
        // V: write directly in packed-B(V^T) layout: n=dim col, k=seq row
        float* base = g_PBV + (size_t)b * (128 * 256 * 64);
        #pragma unroll
        for (int mf = 0; mf < 4; mf++)
            #pragma unroll
            for (int nf = 0; nf < 8; nf++) {
                const int r = (rbg + mf * 16) & 2047, c = cbg + nf * 8;
                base[pbIdx(256, c,     r    )] = rna_tf32(acc[mf][nf][0]);
                base[pbIdx(256, c + 1, r    )] = rna_tf32(acc[mf][nf][1]);
                base[pbIdx(256, c,     r + 8)] = rna_tf32(acc[mf][nf][2]);
                base[pbIdx(256, c + 1, r + 8)] = rna_tf32(acc[mf][nf][3]);
            }
    }
}

__device__ __forceinline__ void do_qk(int b, int q0, int k0)
{
    const float* Ab = g_PAQ + (size_t)b * (128*128*128) + ((size_t)(q0 >> 4) * 128) * 128;
    const float* Bb = g_PBK + (size_t)b * (256*128*64)  + ((size_t)(k0 >> 3) * 128) * 64;

    float acc[4][8][4];
    ZERO_ACC(acc);
    gemm_main(Ab, 128, Bb, 128, DIM / BK, acc);

    float* base = g_PAS + (size_t)b * (128 * 256 * 128);
    const float scale = 0.03125f;
    EPI_COORDS();
    const int rbg = q0 + rb, cbg = k0 + cb;
    #pragma unroll
    for (int mf = 0; mf < 4; mf++)
        #pragma unroll
        for (int nf = 0; nf < 8; nf++) {
            const int r0 = rbg + mf * 16, r1 = r0 + 8;
            const int c  = cbg + nf * 8;
            base[paIdx(256, r0, c    )] = (c     <= r0) ? acc[mf][nf][0] * scale : -CUDART_INF_F;
            base[paIdx(256, r0, c + 1)] = (c + 1 <= r0) ? acc[mf][nf][1] * scale : -CUDART_INF_F;
            base[paIdx(256, r1, c    )] = (c     <= r1) ? acc[mf][nf][2] * scale : -CUDART_INF_F;
            base[paIdx(256, r1, c + 1)] = (c + 1 <= r1) ? acc[mf][nf][3] * scale : -CUDART_INF_F;
        }
}

// ---------------- GEMM kernels ----------------------------------------------
// proj for z=0 (Q) and z=1 (K)
__global__ __launch_bounds__(128, 2)
void proj01_kernel()
{
    do_proj(blockIdx.z, blockIdx.y * BM, blockIdx.x * BN);
}

// fused: 544 qk tiles (triangular x 4 batches) + 512 V-projection tiles
__global__ __launch_bounds__(128, 2)
void qk_projv_kernel()
{
    const int i = blockIdx.x;
    if (i < 544) {
        const int b = i / 136;
        const int t = i - b * 136;
        int qt = (int)((sqrtf(8.0f * t + 1.0f) - 1.0f) * 0.5f);
        while ((qt + 1) * (qt + 2) / 2 <= t) qt++;
        while (qt * (qt + 1) / 2 > t) qt--;
        const int kt = t - qt * (qt + 1) / 2;
        do_qk(b, qt * BM, kt * BN);
    } else {
        const int j = i - 544;                 // 0..511
        do_proj(2, (j >> 3) * BM, (j & 7) * BN);
    }
}

__global__ __launch_bounds__(128, 2)
void pv_kernel(float* __restrict__ out)
{
    const int b  = blockIdx.z;
    const int q0 = (SEQ / BM - 1 - blockIdx.y) * BM;   // heavy tiles first
    const int n0 = blockIdx.x * BN;

    const float* Ab = g_PAS + (size_t)b * (128*256*128) + ((size_t)(q0 >> 4) * 256) * 128;
    const float* Bb = g_PBV + (size_t)b * (128*256*64)  + ((size_t)(n0 >> 3) * 256) * 64;

    float acc[4][8][4];
    ZERO_ACC(acc);
    gemm_main(Ab, 256, Bb, 256, (q0 + BM) / BK, acc);

    float* O = out + (size_t)b * SEQ * DIM;
    EPI_COORDS();
    const int rbg = q0 + rb, cbg = n0 + cb;
    #pragma unroll
    for (int mf = 0; mf < 4; mf++)
        #pragma unroll
        for (int nf = 0; nf < 8; nf++) {
            float* p0 = O + (size_t)(rbg + mf * 16) * DIM + cbg + nf * 8;
            float* p1 = O + (size_t)(rbg + mf * 16 + 8) * DIM + cbg + nf * 8;
            *reinterpret_cast<float2*>(p0) = make_float2(acc[mf][nf][0], acc[mf][nf][1]);
            *reinterpret_cast<float2*>(p1) = make_float2(acc[mf][nf][2], acc[mf][nf][3]);
        }
}

// ---------------- pack kernels ----------------------------------------------
__global__ __launch_bounds__(256)
void pack_x_kernel(const float* __restrict__ x)
{
    __shared__ float sm[16][260];
    const int mb = blockIdx.x;              // 0..511 (16-row group of 8192)
    const int kc = blockIdx.y;              // 0..3 (256-col chunk)
    const float* src = x + (size_t)mb * 16 * DIM + kc * 256;
    for (int i = threadIdx.x; i < 1024; i += 256) {   // 16x256 floats as float4
        int row = i >> 6, c4 = i & 63;
        float4 v = *reinterpret_cast<const float4*>(src + (size_t)row * DIM + c4 * 4);
        *reinterpret_cast<float4*>(&sm[row][c4 * 4]) = v;
    }
    __syncthreads();
    #pragma unroll
    for (int j = 0; j < 4; j++) {
        int s = threadIdx.x + j * 256;      // 0..1023 = 32 kblk x 32 lanes
        int kbl = s >> 5, L = s & 31;
        int r8 = L >> 2, c4 = L & 3;
        float4 v;
        v.x = rna_tf32(sm[r8    ][kbl * 8 + c4    ]);
        v.y = rna_tf32(sm[r8 + 8][kbl * 8 + c4    ]);
        v.z = rna_tf32(sm[r8    ][kbl * 8 + c4 + 4]);
        v.w = rna_tf32(sm[r8 + 8][kbl * 8 + c4 + 4]);
        *reinterpret_cast<float4*>(
            g_PAX + ((size_t)(mb * 128 + kc * 32 + kbl)) * 128 + L * 4) = v;
    }
}

__global__ __launch_bounds__(256)
void pack_w_kernel(const float* __restrict__ Wq,
                   const float* __restrict__ Wk,
                   const float* __restrict__ Wv)
{
    int s = blockIdx.x * 256 + threadIdx.x;
    int L = s & 31, kblk = (s >> 5) & 127, nblk = (s >> 12) & 127, z = s >> 19;
    const float* W = (z == 0) ? Wq : (z == 1) ? Wk : Wv;
    int n = nblk * 8 + (L >> 2), k = kblk * 8 + (L & 3);
    float2 v;
    v.x = rna_tf32(W[(size_t)k * DIM + n]);
    v.y = rna_tf32(W[(size_t)(k + 4) * DIM + n]);
    *reinterpret_cast<float2*>(
        g_PBW + ((size_t)((z * 128 + nblk) * 128 + kblk)) * 64 + L * 2) = v;
}

// ---------------- softmax on packed layout ----------------------------------
__global__ __launch_bounds__(256)
void softmax_kernel()
{
    const int mblk = blockIdx.x;            // 0..127
    const int b    = blockIdx.y;
    float* base = g_PAS + (size_t)b * (128 * 256 * 128) + (size_t)mblk * 256 * 128;
    const int KB = 2 * mblk + 2;                     // blocks holding k <= m0+15
    const int ZB = ((mblk >> 3) << 4) + 16;          // causal boundary blocks

    const int t = threadIdx.x, kp = t >> 5, lane = t & 31;
    const int r0 = lane >> 2;
    __shared__ float red[16][33];
    __shared__ float rowmax[16], rowinv[16];

    float mlo = -CUDART_INF_F, mhi = -CUDART_INF_F;
    for (int kb = kp; kb < KB; kb += 8) {
        float4 f = *reinterpret_cast<const float4*>(base + kb * 128 + lane * 4);
        mlo = fmaxf(mlo, fmaxf(f.x, f.z));
        mhi = fmaxf(mhi, fmaxf(f.y, f.w));
    }
    red[r0][kp * 4 + (lane & 3)] = mlo;
    red[r0 + 8][kp * 4 + (lane & 3)] = mhi;
    __syncthreads();
    if (t < 16) {
        float m = -CUDART_INF_F;
        #pragma unroll
        for (int j = 0; j < 32; j++) m = fmaxf(m, red[t][j]);
        rowmax[t] = m;
    }
    __syncthreads();
    const float Mlo = rowmax[r0], Mhi = rowmax[r0 + 8];

    float slo = 0.0f, shi = 0.0f;
    for (int kb = kp; kb < KB; kb += 8) {
        float4 f = *reinterpret_cast<const float4*>(base + kb * 128 + lane * 4);
        slo += __expf(f.x - Mlo) + __expf(f.z - Mlo);
        shi += __expf(f.y - Mhi) + __expf(f.w - Mhi);
    }
    __syncthreads();
    red[r0][kp * 4 + (lane & 3)] = slo;
    red[r0 + 8][kp * 4 + (lane & 3)] = shi;
    __syncthreads();
    if (t < 16) {
        float ssum = 0.0f;
        #pragma unroll
        for (int j = 0; j < 32; j++) ssum += red[t][j];
        rowinv[t] = 1.0f / ssum;
    }
    __syncthreads();
    const float Ilo = rowinv[r0], Ihi = rowinv[r0 + 8];

    for (int kb = kp; kb < KB; kb += 8) {
        float4 f = *reinterpret_cast<float4*>(base + kb * 128 + lane * 4);
        f.x = rna_tf32(__expf(f.x - Mlo) * Ilo);
        f.z = rna_tf32(__expf(f.z - Mlo) * Ilo);
        f.y = rna_tf32(__expf(f.y - Mhi) * Ihi);
        f.w = rna_tf32(__expf(f.w - Mhi) * Ihi);
        *reinterpret_cast<float4*>(base + kb * 128 + lane * 4) = f;
    }

    // zero the masked blocks [KB, ZB) (read dense by PV)
    const int nz4 = (ZB - KB) * 32;
    float4 z4 = make_float4(0.f, 0.f, 0.f, 0.f);
    for (int i = t; i < nz4; i += 256)
        reinterpret_cast<float4*>(base + KB * 128)[i] = z4;
}

// ---------------- host side --------------------------------------------------
extern "C" void kernel_launch(void* const* d_in, const int* in_sizes, int n_in,
                              void* d_out, int out_size)
{
    const float* x  = (const float*)d_in[0];
    const float* Wq = (const float*)d_in[1];
    const float* Wk = (const float*)d_in[2];
    const float* Wv = (const float*)d_in[3];
    float* out = (float*)d_out;

    static bool configured = false;
    if (!configured) {
        cudaFuncSetAttribute(proj01_kernel,   cudaFuncAttributeMaxDynamicSharedMemorySize, SMEM_BYTES);
        cudaFuncSetAttribute(qk_projv_kernel, cudaFuncAttributeMaxDynamicSharedMemorySize, SMEM_BYTES);
        cudaFuncSetAttribute(pv_kernel,       cudaFuncAttributeMaxDynamicSharedMemorySize, SMEM_BYTES);
        configured = true;
    }

    pack_x_kernel<<<dim3(512, 4), 256>>>(x);
    pack_w_kernel<<<6144, 256>>>(Wq, Wk, Wv);
    proj01_kernel<<<dim3(DIM / BN, MROWS / BM, 2), 128, SMEM_BYTES>>>();
    qk_projv_kernel<<<1056, 128, SMEM_BYTES>>>();      // profiled idx 3
    softmax_kernel<<<dim3(128, BATCH), 256>>>();
    pv_kernel<<<dim3(DIM / BN, SEQ / BM, BATCH), 128, SMEM_BYTES>>>(out);
}

// round 13
// speedup vs baseline: 1.1782x; 1.0819x over previous
#include <cuda_runtime.h>
#include <math_constants.h>
#include <cstdint>

// ===========================================================================
// CasualAttention via tf32 mma.sync (m16n8k8), fragment-packed operands.
//   x[4,2048,1024] fp32, W*[1024,1024] fp32 -> out[4,2048,1024] fp32
// All GEMMs NT: D[m,n] = sum_k A[m,k]*B[n,k].
// A packed: [mblk=M/16][kblk=K/8][lane32][reg4] (512B blocks)
// B packed: [nblk=N/8][kblk=K/8][lane32][reg2] (256B blocks)
// 128 thr/CTA, 4 warps (2x2), warp tile 64x64 (measured-best mainloop).
// Launches: pack_x, pack_w(+flag zero), proj01 (Q,K),
//           attention (qk + projV + softmax + pv, flag-synchronized).
// ===========================================================================

#define BATCH 4
#define SEQ   2048
#define DIM   1024
#define MROWS (BATCH * SEQ)

#define BM 128
#define BN 128
#define BK 32
#define NSTAGES 3
#define STAGE_F 8192                      // floats: A 4096 + B 4096
#define SMEM_BYTES (NSTAGES * STAGE_F * 4)   // 98304

// ---------------- scratch ---------------------------------------------------
__device__ float g_PAX[512 * 128 * 128];              // x packed-A   (32MB)
__device__ float g_PBW[3 * 128 * 128 * 64];           // W^T packed-B (12MB)
__device__ float g_PAQ[(size_t)BATCH * 128 * 128 * 128];   // Q packed-A
__device__ float g_PBK[(size_t)BATCH * 256 * 128 * 64];    // K packed-B
__device__ float g_PBV[(size_t)BATCH * 128 * 256 * 64];    // V^T packed-B
__device__ float g_PAS[(size_t)BATCH * 128 * 256 * 128];   // S/P packed-A (64MB)

// flags: [0,64) cntQK[b][qt], [64,128) cntSM[b][qt], [128,160) cntV[b][nt]
__device__ int g_flags[160];

// ---------------- helpers ---------------------------------------------------
__device__ __forceinline__ uint32_t smem_u32(const void* p) {
    uint32_t a;
    asm("{ .reg .u64 t; cvta.to.shared.u64 t, %1; cvt.u32.u64 %0, t; }"
        : "=r"(a) : "l"(p));
    return a;
}
__device__ __forceinline__ float rna_tf32(float x) {
    float r;
    asm("cvt.rna.tf32.f32 %0, %1;" : "=f"(r) : "f"(x));
    return r;
}
__device__ __forceinline__ void cp16(float* dst, const float* src) {
    uint32_t d = smem_u32(dst);
    asm volatile("cp.async.cg.shared.global [%0], [%1], 16;" :: "r"(d), "l"(src));
}
#define CP_COMMIT() asm volatile("cp.async.commit_group;" ::: "memory")
#define CP_WAIT1()  asm volatile("cp.async.wait_group 1;"  ::: "memory")

__device__ __forceinline__ void mma8(float d[4], float4 a, float2 b) {
    asm volatile(
        "mma.sync.aligned.m16n8k8.row.col.f32.tf32.tf32.f32 "
        "{%0,%1,%2,%3}, {%4,%5,%6,%7}, {%8,%9}, {%0,%1,%2,%3};"
        : "+f"(d[0]), "+f"(d[1]), "+f"(d[2]), "+f"(d[3])
        : "r"(__float_as_uint(a.x)), "r"(__float_as_uint(a.y)),
          "r"(__float_as_uint(a.z)), "r"(__float_as_uint(a.w)),
          "r"(__float_as_uint(b.x)), "r"(__float_as_uint(b.y)));
}

// packed-A float index within one matrix (kbTot = K/8)
__device__ __forceinline__ size_t paIdx(int kbTot, int r, int c) {
    return (((size_t)(r >> 4) * kbTot + (c >> 3)) << 7)
         + (((r & 7) << 2) + (c & 3)) * 4 + ((r >> 3) & 1) + (((c >> 2) & 1) << 1);
}
// packed-B float index (kbTot = K/8)
__device__ __forceinline__ size_t pbIdx(int kbTot, int n, int k) {
    return (((size_t)(n >> 3) * kbTot + (k >> 3)) << 6)
         + (((n & 7) << 2) + (k & 3)) * 2 + ((k >> 2) & 1);
}

// ---------------- grid-wide producer/consumer flags -------------------------
__device__ __forceinline__ void release_add(int* p) {
    __threadfence();
    __syncthreads();
    if (threadIdx.x == 0) atomicAdd(p, 1);
}
__device__ __forceinline__ void wait_cnt(int* p, int target) {
    if (threadIdx.x == 0) {
        int v;
        while (true) {
            asm volatile("ld.acquire.gpu.global.u32 %0, [%1];"
                         : "=r"(v) : "l"(p) : "memory");
            if (v >= target) break;
            __nanosleep(256);
        }
        __threadfence();
    }
    __syncthreads();
}

// ---------------- GEMM mainloop (measured-best shape) ------------------------
// 128 threads = 4 warps (2x2); warp tile 64x64.
__device__ __forceinline__ void load_stage(float* st,
                                           const float* __restrict__ Ab, int ka,
                                           const float* __restrict__ Bb, int kbt,
                                           int kb0)
{
    const int t = threadIdx.x;
    {
        const int mb = t >> 4, c0 = t & 15;
        const float* src = Ab + ((size_t)mb * ka + kb0) * 128;
        float* dst = st + mb * 512;
        #pragma unroll
        for (int j = 0; j < 8; j++)
            cp16(dst + (c0 + 16 * j) * 4, src + (c0 + 16 * j) * 4);
    }
    {
        const int nb = t >> 3, c0 = t & 7;
        const float* src = Bb + ((size_t)nb * kbt + kb0) * 64;
        float* dst = st + 4096 + nb * 256;
        #pragma unroll
        for (int j = 0; j < 8; j++)
            cp16(dst + (c0 + 8 * j) * 4, src + (c0 + 8 * j) * 4);
    }
}

__device__ __forceinline__ void gemm_main(const float* __restrict__ Ab, int ka,
                                          const float* __restrict__ Bb, int kbt,
                                          int kIters, float acc[4][8][4])
{
    extern __shared__ float smem[];
    const int wid  = threadIdx.x >> 5;
    const int lane = threadIdx.x & 31;

    #pragma unroll
    for (int s = 0; s < NSTAGES - 1; s++) {
        load_stage(smem + s * STAGE_F, Ab, ka, Bb, kbt, s * 4);
        CP_COMMIT();
    }

    int slot = 0;
    for (int it = 0; it < kIters; it++) {
        CP_WAIT1();
        __syncthreads();

        const int nk = it + NSTAGES - 1;
        if (nk < kIters) {
            int ns = nk % NSTAGES;
            load_stage(smem + ns * STAGE_F, Ab, ka, Bb, kbt, nk * 4);
        }
        CP_COMMIT();

        const float* sA = smem + slot * STAGE_F + ((wid >> 1) * 4) * 512;
        const float* sB = smem + slot * STAGE_F + 4096 + ((wid & 1) * 8) * 256;

        #pragma unroll
        for (int ks = 0; ks < 4; ks++) {
            float4 av[4];
            #pragma unroll
            for (int mf = 0; mf < 4; mf++)
                av[mf] = *reinterpret_cast<const float4*>(sA + mf * 512 + ks * 128 + lane * 4);
            float2 bv[8];
            #pragma unroll
            for (int nf = 0; nf < 8; nf++)
                bv[nf] = *reinterpret_cast<const float2*>(sB + nf * 256 + ks * 64 + lane * 2);
            #pragma unroll
            for (int mf = 0; mf < 4; mf++)
                #pragma unroll
                for (int nf = 0; nf < 8; nf++)
                    mma8(acc[mf][nf], av[mf], bv[nf]);
        }
        if (++slot == NSTAGES) slot = 0;
    }
}

#define ZERO_ACC(acc) do { \
    _Pragma("unroll") for (int _i = 0; _i < 4; _i++) \
    _Pragma("unroll") for (int _j = 0; _j < 8; _j++) \
    _Pragma("unroll") for (int _l = 0; _l < 4; _l++) acc[_i][_j][_l] = 0.0f; \
} while (0)

// epilogue coordinates (4-warp 2x2, warp tile 64x64)
#define EPI_COORDS() \
    const int wid = threadIdx.x >> 5, lane = threadIdx.x & 31; \
    const int g = lane >> 2, tg = lane & 3; \
    const int rb = ((wid >> 1) << 6) + g; \
    const int cb = ((wid & 1) << 6) + 2 * tg

// ---------------- role bodies ------------------------------------------------
__device__ __forceinline__ void do_proj(int z, int m0, int n0)
{
    const float* Ab = g_PAX + ((size_t)(m0 >> 4) * 128) * 128;
    const float* Bb = g_PBW + ((size_t)(z * 128 + (n0 >> 3)) * 128) * 64;

    float acc[4][8][4];
    ZERO_ACC(acc);
    gemm_main(Ab, 128, Bb, 128, DIM / BK, acc);

    EPI_COORDS();
    const int b = m0 >> 11;
    const int rbg = m0 + rb, cbg = n0 + cb;

    if (z == 0) {
        float* base = g_PAQ + (size_t)b * (128 * 128 * 128);
        #pragma unroll
        for (int mf = 0; mf < 4; mf++)
            #pragma unroll
            for (int nf = 0; nf < 8; nf++) {
                const int r = (rbg + mf * 16) & 2047, c = cbg + nf * 8;
                base[paIdx(128, r,     c    )] = rna_tf32(acc[mf][nf][0]);
                base[paIdx(128, r,     c + 1)] = rna_tf32(acc[mf][nf][1]);
                base[paIdx(128, r + 8, c    )] = rna_tf32(acc[mf][nf][2]);
                base[paIdx(128, r + 8, c + 1)] = rna_tf32(acc[mf][nf][3]);
            }
    } else if (z == 1) {
        float* base = g_PBK + (size_t)b * (256 * 128 * 64);
        #pragma unroll
        for (int mf = 0; mf < 4; mf++)
            #pragma unroll
            for (int nf = 0; nf < 8; nf++) {
                const int r = (rbg + mf * 16) & 2047, c = cbg + nf * 8;
                base[pbIdx(128, r,     c    )] = rna_tf32(acc[mf][nf][0]);
                base[pbIdx(128, r,     c + 1)] = rna_tf32(acc[mf][nf][1]);
                base[pbIdx(128, r + 8, c    )] = rna_tf32(acc[mf][nf][2]);
                base[pbIdx(128, r + 8, c + 1)] = rna_tf32(acc[mf][nf][3]);
            }
    } else {
        // V: write directly in packed-B(V^T) layout: n=dim col, k=seq row
        float* base = g_PBV + (size_t)b * (128 * 256 * 64);
        #pragma unroll
        for (int mf = 0; mf < 4; mf++)
            #pragma unroll
            for (int nf = 0; nf < 8; nf++) {
                const int r = (rbg + mf * 16) & 2047, c = cbg + nf * 8;
                base[pbIdx(256, c,     r    )] = rna_tf32(acc[mf][nf][0]);
                base[pbIdx(256, c + 1, r    )] = rna_tf32(acc[mf][nf][1]);
                base[pbIdx(256, c,     r + 8)] = rna_tf32(acc[mf][nf][2]);
                base[pbIdx(256, c + 1, r + 8)] = rna_tf32(acc[mf][nf][3]);
            }
    }
}

__device__ __forceinline__ void do_qk(int b, int q0, int k0)
{
    const float* Ab = g_PAQ + (size_t)b * (128*128*128) + ((size_t)(q0 >> 4) * 128) * 128;
    const float* Bb = g_PBK + (size_t)b * (256*128*64)  + ((size_t)(k0 >> 3) * 128) * 64;

    float acc[4][8][4];
    ZERO_ACC(acc);
    gemm_main(Ab, 128, Bb, 128, DIM / BK, acc);

    float* base = g_PAS + (size_t)b * (128 * 256 * 128);
    const float scale = 0.03125f;
    EPI_COORDS();
    const int rbg = q0 + rb, cbg = k0 + cb;
    #pragma unroll
    for (int mf = 0; mf < 4; mf++)
        #pragma unroll
        for (int nf = 0; nf < 8; nf++) {
            const int r0 = rbg + mf * 16, r1 = r0 + 8;
            const int c  = cbg + nf * 8;
            base[paIdx(256, r0, c    )] = (c     <= r0) ? acc[mf][nf][0] * scale : -CUDART_INF_F;
            base[paIdx(256, r0, c + 1)] = (c + 1 <= r0) ? acc[mf][nf][1] * scale : -CUDART_INF_F;
            base[paIdx(256, r1, c    )] = (c     <= r1) ? acc[mf][nf][2] * scale : -CUDART_INF_F;
            base[paIdx(256, r1, c + 1)] = (c + 1 <= r1) ? acc[mf][nf][3] * scale : -CUDART_INF_F;
        }
}

__device__ __forceinline__ void do_pv(float* __restrict__ out, int b, int q0, int n0)
{
    const float* Ab = g_PAS + (size_t)b * (128*256*128) + ((size_t)(q0 >> 4) * 256) * 128;
    const float* Bb = g_PBV + (size_t)b * (128*256*64)  + ((size_t)(n0 >> 3) * 256) * 64;

    float acc[4][8][4];
    ZERO_ACC(acc);
    gemm_main(Ab, 256, Bb, 256, (q0 + BM) / BK, acc);

    float* O = out + (size_t)b * SEQ * DIM;
    EPI_COORDS();
    const int rbg = q0 + rb, cbg = n0 + cb;
    #pragma unroll
    for (int mf = 0; mf < 4; mf++)
        #pragma unroll
        for (int nf = 0; nf < 8; nf++) {
            float* p0 = O + (size_t)(rbg + mf * 16) * DIM + cbg + nf * 8;
            float* p1 = O + (size_t)(rbg + mf * 16 + 8) * DIM + cbg + nf * 8;
            *reinterpret_cast<float2*>(p0) = make_float2(acc[mf][nf][0], acc[mf][nf][1]);
            *reinterpret_cast<float2*>(p1) = make_float2(acc[mf][nf][2], acc[mf][nf][3]);
        }
}

// softmax on packed layout, 128 threads
__device__ __forceinline__ void softmax_role(int b, int mblk)
{
    float* base = g_PAS + (size_t)b * (128 * 256 * 128) + (size_t)mblk * 256 * 128;
    const int KB = 2 * mblk + 2;                     // blocks holding k <= m0+15
    const int ZB = ((mblk >> 3) << 4) + 16;          // causal boundary blocks

    const int t = threadIdx.x, kp = t >> 5, lane = t & 31;
    const int r0 = lane >> 2, ci = kp * 4 + (lane & 3);
    __shared__ float red[16][17];
    __shared__ float stat[16];

    float mlo = -CUDART_INF_F, mhi = -CUDART_INF_F;
    for (int kb = kp; kb < KB; kb += 4) {
        float4 f = *reinterpret_cast<const float4*>(base + kb * 128 + lane * 4);
        mlo = fmaxf(mlo, fmaxf(f.x, f.z));
        mhi = fmaxf(mhi, fmaxf(f.y, f.w));
    }
    red[r0][ci] = mlo;
    red[r0 + 8][ci] = mhi;
    __syncthreads();
    if (t < 16) {
        float m = -CUDART_INF_F;
        #pragma unroll
        for (int j = 0; j < 16; j++) m = fmaxf(m, red[t][j]);
        stat[t] = m;
    }
    __syncthreads();
    const float Mlo = stat[r0], Mhi = stat[r0 + 8];

    float slo = 0.0f, shi = 0.0f;
    for (int kb = kp; kb < KB; kb += 4) {
        float4 f = *reinterpret_cast<const float4*>(base + kb * 128 + lane * 4);
        slo += __expf(f.x - Mlo) + __expf(f.z - Mlo);
        shi += __expf(f.y - Mhi) + __expf(f.w - Mhi);
    }
    __syncthreads();
    red[r0][ci] = slo;
    red[r0 + 8][ci] = shi;
    __syncthreads();
    if (t < 16) {
        float ssum = 0.0f;
        #pragma unroll
        for (int j = 0; j < 16; j++) ssum += red[t][j];
        stat[t] = 1.0f / ssum;
    }
    __syncthreads();
    const float Ilo = stat[r0], Ihi = stat[r0 + 8];

    for (int kb = kp; kb < KB; kb += 4) {
        float4 f = *reinterpret_cast<float4*>(base + kb * 128 + lane * 4);
        f.x = rna_tf32(__expf(f.x - Mlo) * Ilo);
        f.z = rna_tf32(__expf(f.z - Mlo) * Ilo);
        f.y = rna_tf32(__expf(f.y - Mhi) * Ihi);
        f.w = rna_tf32(__expf(f.w - Mhi) * Ihi);
        *reinterpret_cast<float4*>(base + kb * 128 + lane * 4) = f;
    }

    // zero the masked blocks [KB, ZB) (read dense by PV)
    const int nz4 = (ZB - KB) * 32;
    float4 z4 = make_float4(0.f, 0.f, 0.f, 0.f);
    for (int i = t; i < nz4; i += 128)
        reinterpret_cast<float4*>(base + KB * 128)[i] = z4;
}

// ---------------- GEMM kernels ----------------------------------------------
// proj for z=0 (Q) and z=1 (K)
__global__ __launch_bounds__(128, 2)
void proj01_kernel()
{
    do_proj(blockIdx.z, blockIdx.y * BM, blockIdx.x * BN);
}

// fused attention: qk [0,544) + projV [544,1056) + softmax [1056,1568)
//                  + pv [1568,2080), flag-synchronized, heavy-qt-first.
__global__ __launch_bounds__(128, 2)
void attention_kernel(float* __restrict__ out)
{
    const int bid = blockIdx.x;
    if (bid < 544) {
        const int tri = bid >> 2, b = bid & 3;
        const int j = 135 - tri;                    // descending qt
        int qt = (int)((sqrtf(8.0f * j + 1.0f) - 1.0f) * 0.5f);
        while ((qt + 1) * (qt + 2) / 2 <= j) qt++;
        while (qt * (qt + 1) / 2 > j) qt--;
        const int kt = j - qt * (qt + 1) / 2;
        do_qk(b, qt * BM, kt * BN);
        release_add(&g_flags[b * 16 + qt]);                 // cntQK
    } else if (bid < 1056) {
        const int v = bid - 544;
        const int mt = v >> 3, nt = v & 7;                  // mt 0..63 global
        do_proj(2, mt * BM, nt * BN);
        release_add(&g_flags[128 + (mt >> 4) * 8 + nt]);    // cntV
    } else if (bid < 1568) {
        const int s = bid - 1056;
        const int b = s & 3, mblk = 127 - (s >> 2);         // descending
        const int qt = mblk >> 3;
        wait_cnt(&g_flags[b * 16 + qt], qt + 1);
        softmax_role(b, mblk);
        release_add(&g_flags[64 + b * 16 + qt]);            // cntSM
    } else {
        const int s = bid - 1568;
        const int qt = 15 - (s >> 5);                       // heavy first
        const int rem = s & 31, b = rem & 3, nt = rem >> 2;
        wait_cnt(&g_flags[64 + b * 16 + qt], 8);
        wait_cnt(&g_flags[128 + b * 8 + nt], 16);
        do_pv(out, b, qt * BM, nt * BN);
    }
}

// ---------------- pack kernels ----------------------------------------------
__global__ __launch_bounds__(256)
void pack_x_kernel(const float* __restrict__ x)
{
    __shared__ float sm[16][260];
    const int mb = blockIdx.x;              // 0..511 (16-row group of 8192)
    const int kc = blockIdx.y;              // 0..3 (256-col chunk)
    const float* src = x + (size_t)mb * 16 * DIM + kc * 256;
    for (int i = threadIdx.x; i < 1024; i += 256) {   // 16x256 floats as float4
        int row = i >> 6, c4 = i & 63;
        float4 v = *reinterpret_cast<const float4*>(src + (size_t)row * DIM + c4 * 4);
        *reinterpret_cast<float4*>(&sm[row][c4 * 4]) = v;
    }
    __syncthreads();
    #pragma unroll
    for (int j = 0; j < 4; j++) {
        int s = threadIdx.x + j * 256;      // 0..1023 = 32 kblk x 32 lanes
        int kbl = s >> 5, L = s & 31;
        int r8 = L >> 2, c4 = L & 3;
        float4 v;
        v.x = rna_tf32(sm[r8    ][kbl * 8 + c4    ]);
        v.y = rna_tf32(sm[r8 + 8][kbl * 8 + c4    ]);
        v.z = rna_tf32(sm[r8    ][kbl * 8 + c4 + 4]);
        v.w = rna_tf32(sm[r8 + 8][kbl * 8 + c4 + 4]);
        *reinterpret_cast<float4*>(
            g_PAX + ((size_t)(mb * 128 + kc * 32 + kbl)) * 128 + L * 4) = v;
    }
}

__global__ __launch_bounds__(256)
void pack_w_kernel(const float* __restrict__ Wq,
                   const float* __restrict__ Wk,
                   const float* __restrict__ Wv)
{
    // block 0 zeroes the stage flags (replayed every graph iteration)
    if (blockIdx.x == 0 && threadIdx.x < 160) g_flags[threadIdx.x] = 0;

    int s = blockIdx.x * 256 + threadIdx.x;
    int L = s & 31, kblk = (s >> 5) & 127, nblk = (s >> 12) & 127, z = s >> 19;
    const float* W = (z == 0) ? Wq : (z == 1) ? Wk : Wv;
    int n = nblk * 8 + (L >> 2), k = kblk * 8 + (L & 3);
    float2 v;
    v.x = rna_tf32(W[(size_t)k * DIM + n]);
    v.y = rna_tf32(W[(size_t)(k + 4) * DIM + n]);
    *reinterpret_cast<float2*>(
        g_PBW + ((size_t)((z * 128 + nblk) * 128 + kblk)) * 64 + L * 2) = v;
}

// ---------------- host side --------------------------------------------------
extern "C" void kernel_launch(void* const* d_in, const int* in_sizes, int n_in,
                              void* d_out, int out_size)
{
    const float* x  = (const float*)d_in[0];
    const float* Wq = (const float*)d_in[1];
    const float* Wk = (const float*)d_in[2];
    const float* Wv = (const float*)d_in[3];
    float* out = (float*)d_out;

    static bool configured = false;
    if (!configured) {
        cudaFuncSetAttribute(proj01_kernel,    cudaFuncAttributeMaxDynamicSharedMemorySize, SMEM_BYTES);
        cudaFuncSetAttribute(attention_kernel, cudaFuncAttributeMaxDynamicSharedMemorySize, SMEM_BYTES);
        configured = true;
    }

    pack_x_kernel<<<dim3(512, 4), 256>>>(x);
    pack_w_kernel<<<6144, 256>>>(Wq, Wk, Wv);
    proj01_kernel<<<dim3(DIM / BN, MROWS / BM, 2), 128, SMEM_BYTES>>>();
    attention_kernel<<<2080, 128, SMEM_BYTES>>>(out);   // profiled idx 3
}

// round 14
// speedup vs baseline: 1.1936x; 1.0130x over previous
#include <cuda_runtime.h>
#include <math_constants.h>
#include <cstdint>

// ===========================================================================
// CasualAttention via tf32 mma.sync (m16n8k8), fragment-packed operands.
//   x[4,2048,1024] fp32, W*[1024,1024] fp32 -> out[4,2048,1024] fp32
// All GEMMs NT: D[m,n] = sum_k A[m,k]*B[n,k].
// A packed: [mblk=M/16][kblk=K/8][lane32][reg4] (512B blocks)
// B packed: [nblk=N/8][kblk=K/8][lane32][reg2] (256B blocks)
// 128 thr/CTA, 4 warps (2x2), warp tile 64x64 (measured-best mainloop).
// Launches: pack_x, pack_w(+flag zero),
//           mega (projK + projQ + qk + projV + softmax + pv, flag-synced).
// ===========================================================================

#define BATCH 4
#define SEQ   2048
#define DIM   1024
#define MROWS (BATCH * SEQ)

#define BM 128
#define BN 128
#define BK 32
#define NSTAGES 3
#define STAGE_F 8192                      // floats: A 4096 + B 4096
#define SMEM_BYTES (NSTAGES * STAGE_F * 4)   // 98304

// ---------------- scratch ---------------------------------------------------
__device__ float g_PAX[512 * 128 * 128];              // x packed-A   (32MB)
__device__ float g_PBW[3 * 128 * 128 * 64];           // W^T packed-B (12MB)
__device__ float g_PAQ[(size_t)BATCH * 128 * 128 * 128];   // Q packed-A
__device__ float g_PBK[(size_t)BATCH * 256 * 128 * 64];    // K packed-B
__device__ float g_PBV[(size_t)BATCH * 128 * 256 * 64];    // V^T packed-B
__device__ float g_PAS[(size_t)BATCH * 128 * 256 * 128];   // S/P packed-A (64MB)

// flags: [0,64) cntQ[b][qt] (tgt 8), [64,128) cntK[b][kt] (tgt 8),
//        [128,192) cntQK[b][qt] (tgt qt+1), [192,256) cntSM[b][qt] (tgt 8),
//        [256,288) cntV[b][nt] (tgt 16)
__device__ int g_flags[288];

// ---------------- helpers ---------------------------------------------------
__device__ __forceinline__ uint32_t smem_u32(const void* p) {
    uint32_t a;
    asm("{ .reg .u64 t; cvta.to.shared.u64 t, %1; cvt.u32.u64 %0, t; }"
        : "=r"(a) : "l"(p));
    return a;
}
__device__ __forceinline__ float rna_tf32(float x) {
    float r;
    asm("cvt.rna.tf32.f32 %0, %1;" : "=f"(r) : "f"(x));
    return r;
}
__device__ __forceinline__ void cp16(float* dst, const float* src) {
    uint32_t d = smem_u32(dst);
    asm volatile("cp.async.cg.shared.global [%0], [%1], 16;" :: "r"(d), "l"(src));
}
#define CP_COMMIT() asm volatile("cp.async.commit_group;" ::: "memory")
#define CP_WAIT1()  asm volatile("cp.async.wait_group 1;"  ::: "memory")

__device__ __forceinline__ void mma8(float d[4], float4 a, float2 b) {
    asm volatile(
        "mma.sync.aligned.m16n8k8.row.col.f32.tf32.tf32.f32 "
        "{%0,%1,%2,%3}, {%4,%5,%6,%7}, {%8,%9}, {%0,%1,%2,%3};"
        : "+f"(d[0]), "+f"(d[1]), "+f"(d[2]), "+f"(d[3])
        : "r"(__float_as_uint(a.x)), "r"(__float_as_uint(a.y)),
          "r"(__float_as_uint(a.z)), "r"(__float_as_uint(a.w)),
          "r"(__float_as_uint(b.x)), "r"(__float_as_uint(b.y)));
}

// packed-A float index within one matrix (kbTot = K/8)
__device__ __forceinline__ size_t paIdx(int kbTot, int r, int c) {
    return (((size_t)(r >> 4) * kbTot + (c >> 3)) << 7)
         + (((r & 7) << 2) + (c & 3)) * 4 + ((r >> 3) & 1) + (((c >> 2) & 1) << 1);
}
// packed-B float index (kbTot = K/8)
__device__ __forceinline__ size_t pbIdx(int kbTot, int n, int k) {
    return (((size_t)(n >> 3) * kbTot + (k >> 3)) << 6)
         + (((n & 7) << 2) + (k & 3)) * 2 + ((k >> 2) & 1);
}

// ---------------- grid-wide producer/consumer flags -------------------------
__device__ __forceinline__ void release_add(int* p) {
    __threadfence();
    __syncthreads();
    if (threadIdx.x == 0) atomicAdd(p, 1);
}
__device__ __forceinline__ void wait_cnt(int* p, int target) {
    if (threadIdx.x == 0) {
        int v;
        while (true) {
            asm volatile("ld.acquire.gpu.global.u32 %0, [%1];"
                         : "=r"(v) : "l"(p) : "memory");
            if (v >= target) break;
            __nanosleep(256);
        }
        __threadfence();
    }
    __syncthreads();
}

// ---------------- GEMM mainloop (measured-best shape) ------------------------
// 128 threads = 4 warps (2x2); warp tile 64x64.
__device__ __forceinline__ void load_stage(float* st,
                                           const float* __restrict__ Ab, int ka,
                                           const float* __restrict__ Bb, int kbt,
                                           int kb0)
{
    const int t = threadIdx.x;
    {
        const int mb = t >> 4, c0 = t & 15;
        const float* src = Ab + ((size_t)mb * ka + kb0) * 128;
        float* dst = st + mb * 512;
        #pragma unroll
        for (int j = 0; j < 8; j++)
            cp16(dst + (c0 + 16 * j) * 4, src + (c0 + 16 * j) * 4);
    }
    {
        const int nb = t >> 3, c0 = t & 7;
        const float* src = Bb + ((size_t)nb * kbt + kb0) * 64;
        float* dst = st + 4096 + nb * 256;
        #pragma unroll
        for (int j = 0; j < 8; j++)
            cp16(dst + (c0 + 8 * j) * 4, src + (c0 + 8 * j) * 4);
    }
}

__device__ __forceinline__ void gemm_main(const float* __restrict__ Ab, int ka,
                                          const float* __restrict__ Bb, int kbt,
                                          int kIters, float acc[4][8][4])
{
    extern __shared__ float smem[];
    const int wid  = threadIdx.x >> 5;
    const int lane = threadIdx.x & 31;

    #pragma unroll
    for (int s = 0; s < NSTAGES - 1; s++) {
        load_stage(smem + s * STAGE_F, Ab, ka, Bb, kbt, s * 4);
        CP_COMMIT();
    }

    int slot = 0;
    for (int it = 0; it < kIters; it++) {
        CP_WAIT1();
        __syncthreads();

        const int nk = it + NSTAGES - 1;
        if (nk < kIters) {
            int ns = nk % NSTAGES;
            load_stage(smem + ns * STAGE_F, Ab, ka, Bb, kbt, nk * 4);
        }
        CP_COMMIT();

        const float* sA = smem + slot * STAGE_F + ((wid >> 1) * 4) * 512;
        const float* sB = smem + slot * STAGE_F + 4096 + ((wid & 1) * 8) * 256;

        #pragma unroll
        for (int ks = 0; ks < 4; ks++) {
            float4 av[4];
            #pragma unroll
            for (int mf = 0; mf < 4; mf++)
                av[mf] = *reinterpret_cast<const float4*>(sA + mf * 512 + ks * 128 + lane * 4);
            float2 bv[8];
            #pragma unroll
            for (int nf = 0; nf < 8; nf++)
                bv[nf] = *reinterpret_cast<const float2*>(sB + nf * 256 + ks * 64 + lane * 2);
            #pragma unroll
            for (int mf = 0; mf < 4; mf++)
                #pragma unroll
                for (int nf = 0; nf < 8; nf++)
                    mma8(acc[mf][nf], av[mf], bv[nf]);
        }
        if (++slot == NSTAGES) slot = 0;
    }
}

#define ZERO_ACC(acc) do { \
    _Pragma("unroll") for (int _i = 0; _i < 4; _i++) \
    _Pragma("unroll") for (int _j = 0; _j < 8; _j++) \
    _Pragma("unroll") for (int _l = 0; _l < 4; _l++) acc[_i][_j][_l] = 0.0f; \
} while (0)

// epilogue coordinates (4-warp 2x2, warp tile 64x64)
#define EPI_COORDS() \
    const int wid = threadIdx.x >> 5, lane = threadIdx.x & 31; \
    const int g = lane >> 2, tg = lane & 3; \
    const int rb = ((wid >> 1) << 6) + g; \
    const int cb = ((wid & 1) << 6) + 2 * tg

// ---------------- role bodies ------------------------------------------------
__device__ __forceinline__ void do_proj(int z, int m0, int n0)
{
    const float* Ab = g_PAX + ((size_t)(m0 >> 4) * 128) * 128;
    const float* Bb = g_PBW + ((size_t)(z * 128 + (n0 >> 3)) * 128) * 64;

    float acc[4][8][4];
    ZERO_ACC(acc);
    gemm_main(Ab, 128, Bb, 128, DIM / BK, acc);

    EPI_COORDS();
    const int b = m0 >> 11;
    const int rbg = m0 + rb, cbg = n0 + cb;

    if (z == 0) {
        float* base = g_PAQ + (size_t)b * (128 * 128 * 128);
        #pragma unroll
        for (int mf = 0; mf < 4; mf++)
            #pragma unroll
            for (int nf = 0; nf < 8; nf++) {
                const int r = (rbg + mf * 16) & 2047, c = cbg + nf * 8;
                base[paIdx(128, r,     c    )] = rna_tf32(acc[mf][nf][0]);
                base[paIdx(128, r,     c + 1)] = rna_tf32(acc[mf][nf][1]);
                base[paIdx(128, r + 8, c    )] = rna_tf32(acc[mf][nf][2]);
                base[paIdx(128, r + 8, c + 1)] = rna_tf32(acc[mf][nf][3]);
            }
    } else if (z == 1) {
        float* base = g_PBK + (size_t)b * (256 * 128 * 64);
        #pragma unroll
        for (int mf = 0; mf < 4; mf++)
            #pragma unroll
            for (int nf = 0; nf < 8; nf++) {
                const int r = (rbg + mf * 16) & 2047, c = cbg + nf * 8;
                base[pbIdx(128, r,     c    )] = rna_tf32(acc[mf][nf][0]);
                base[pbIdx(128, r,     c + 1)] = rna_tf32(acc[mf][nf][1]);
                base[pbIdx(128, r + 8, c    )] = rna_tf32(acc[mf][nf][2]);
                base[pbIdx(128, r + 8, c + 1)] = rna_tf32(acc[mf][nf][3]);
            }
    } else {
        // V: write directly in packed-B(V^T) layout: n=dim col, k=seq row
        float* base = g_PBV + (size_t)b * (128 * 256 * 64);
        #pragma unroll
        for (int mf = 0; mf < 4; mf++)
            #pragma unroll
            for (int nf = 0; nf < 8; nf++) {
                const int r = (rbg + mf * 16) & 2047, c = cbg + nf * 8;
                base[pbIdx(256, c,     r    )] = rna_tf32(acc[mf][nf][0]);
                base[pbIdx(256, c + 1, r    )] = rna_tf32(acc[mf][nf][1]);
                base[pbIdx(256, c,     r + 8)] = rna_tf32(acc[mf][nf][2]);
                base[pbIdx(256, c + 1, r + 8)] = rna_tf32(acc[mf][nf][3]);
            }
    }
}

__device__ __forceinline__ void do_qk(int b, int q0, int k0)
{
    const float* Ab = g_PAQ + (size_t)b * (128*128*128) + ((size_t)(q0 >> 4) * 128) * 128;
    const float* Bb = g_PBK + (size_t)b * (256*128*64)  + ((size_t)(k0 >> 3) * 128) * 64;

    float acc[4][8][4];
    ZERO_ACC(acc);
    gemm_main(Ab, 128, Bb, 128, DIM / BK, acc);

    float* base = g_PAS + (size_t)b * (128 * 256 * 128);
    const float scale = 0.03125f;
    EPI_COORDS();
    const int rbg = q0 + rb, cbg = k0 + cb;
    #pragma unroll
    for (int mf = 0; mf < 4; mf++)
        #pragma unroll
        for (int nf = 0; nf < 8; nf++) {
            const int r0 = rbg + mf * 16, r1 = r0 + 8;
            const int c  = cbg + nf * 8;
            base[paIdx(256, r0, c    )] = (c     <= r0) ? acc[mf][nf][0] * scale : -CUDART_INF_F;
            base[paIdx(256, r0, c + 1)] = (c + 1 <= r0) ? acc[mf][nf][1] * scale : -CUDART_INF_F;
            base[paIdx(256, r1, c    )] = (c     <= r1) ? acc[mf][nf][2] * scale : -CUDART_INF_F;
            base[paIdx(256, r1, c + 1)] = (c + 1 <= r1) ? acc[mf][nf][3] * scale : -CUDART_INF_F;
        }
}

__device__ __forceinline__ void do_pv(float* __restrict__ out, int b, int q0, int n0)
{
    const float* Ab = g_PAS + (size_t)b * (128*256*128) + ((size_t)(q0 >> 4) * 256) * 128;
    const float* Bb = g_PBV + (size_t)b * (128*256*64)  + ((size_t)(n0 >> 3) * 256) * 64;

    float acc[4][8][4];
    ZERO_ACC(acc);
    gemm_main(Ab, 256, Bb, 256, (q0 + BM) / BK, acc);

    float* O = out + (size_t)b * SEQ * DIM;
    EPI_COORDS();
    const int rbg = q0 + rb, cbg = n0 + cb;
    #pragma unroll
    for (int mf = 0; mf < 4; mf++)
        #pragma unroll
        for (int nf = 0; nf < 8; nf++) {
            float* p0 = O + (size_t)(rbg + mf * 16) * DIM + cbg + nf * 8;
            float* p1 = O + (size_t)(rbg + mf * 16 + 8) * DIM + cbg + nf * 8;
            *reinterpret_cast<float2*>(p0) = make_float2(acc[mf][nf][0], acc[mf][nf][1]);
            *reinterpret_cast<float2*>(p1) = make_float2(acc[mf][nf][2], acc[mf][nf][3]);
        }
}

// softmax on packed layout, 128 threads
__device__ __forceinline__ void softmax_role(int b, int mblk)
{
    float* base = g_PAS + (size_t)b * (128 * 256 * 128) + (size_t)mblk * 256 * 128;
    const int KB = 2 * mblk + 2;                     // blocks holding k <= m0+15
    const int ZB = ((mblk >> 3) << 4) + 16;          // causal boundary blocks

    const int t = threadIdx.x, kp = t >> 5, lane = t & 31;
    const int r0 = lane >> 2, ci = kp * 4 + (lane & 3);
    __shared__ float red[16][17];
    __shared__ float stat[16];

    float mlo = -CUDART_INF_F, mhi = -CUDART_INF_F;
    for (int kb = kp; kb < KB; kb += 4) {
        float4 f = *reinterpret_cast<const float4*>(base + kb * 128 + lane * 4);
        mlo = fmaxf(mlo, fmaxf(f.x, f.z));
        mhi = fmaxf(mhi, fmaxf(f.y, f.w));
    }
    red[r0][ci] = mlo;
    red[r0 + 8][ci] = mhi;
    __syncthreads();
    if (t < 16) {
        float m = -CUDART_INF_F;
        #pragma unroll
        for (int j = 0; j < 16; j++) m = fmaxf(m, red[t][j]);
        stat[t] = m;
    }
    __syncthreads();
    const float Mlo = stat[r0], Mhi = stat[r0 + 8];

    float slo = 0.0f, shi = 0.0f;
    for (int kb = kp; kb < KB; kb += 4) {
        float4 f = *reinterpret_cast<const float4*>(base + kb * 128 + lane * 4);
        slo += __expf(f.x - Mlo) + __expf(f.z - Mlo);
        shi += __expf(f.y - Mhi) + __expf(f.w - Mhi);
    }
    __syncthreads();
    red[r0][ci] = slo;
    red[r0 + 8][ci] = shi;
    __syncthreads();
    if (t < 16) {
        float ssum = 0.0f;
        #pragma unroll
        for (int j = 0; j < 16; j++) ssum += red[t][j];
        stat[t] = 1.0f / ssum;
    }
    __syncthreads();
    const float Ilo = stat[r0], Ihi = stat[r0 + 8];

    for (int kb = kp; kb < KB; kb += 4) {
        float4 f = *reinterpret_cast<float4*>(base + kb * 128 + lane * 4);
        f.x = rna_tf32(__expf(f.x - Mlo) * Ilo);
        f.z = rna_tf32(__expf(f.z - Mlo) * Ilo);
        f.y = rna_tf32(__expf(f.y - Mhi) * Ihi);
        f.w = rna_tf32(__expf(f.w - Mhi) * Ihi);
        *reinterpret_cast<float4*>(base + kb * 128 + lane * 4) = f;
    }

    // zero the masked blocks [KB, ZB) (read dense by PV)
    const int nz4 = (ZB - KB) * 32;
    float4 z4 = make_float4(0.f, 0.f, 0.f, 0.f);
    for (int i = t; i < nz4; i += 128)
        reinterpret_cast<float4*>(base + KB * 128)[i] = z4;
}

// ---------------- mega kernel ------------------------------------------------
// bids: [0,512) projK  | [512,1024) projQ (desc qt) | [1024,1568) qk (desc qt)
//       [1568,2080) projV | [2080,2592) softmax (desc) | [2592,3104) pv (desc)
__global__ __launch_bounds__(128, 2)
void mega_kernel(float* __restrict__ out)
{
    const int bid = blockIdx.x;
    if (bid < 512) {
        const int mt = bid >> 3, n0 = (bid & 7) * BN;      // mt = b*16+kt
        do_proj(1, mt * BM, n0);
        release_add(&g_flags[64 + mt]);                    // cntK
    } else if (bid < 1024) {
        const int j = bid - 512;
        const int mt = 63 - (j >> 3), n0 = (j & 7) * BN;   // desc qt
        do_proj(0, mt * BM, n0);
        release_add(&g_flags[mt]);                         // cntQ
    } else if (bid < 1568) {
        const int t = bid - 1024;
        const int tri = t >> 2, b = t & 3;
        const int jj = 135 - tri;                          // descending qt
        int qt = (int)((sqrtf(8.0f * jj + 1.0f) - 1.0f) * 0.5f);
        while ((qt + 1) * (qt + 2) / 2 <= jj) qt++;
        while (qt * (qt + 1) / 2 > jj) qt--;
        const int kt = jj - qt * (qt + 1) / 2;
        wait_cnt(&g_flags[b * 16 + qt], 8);                // Q rows ready
        wait_cnt(&g_flags[64 + b * 16 + kt], 8);           // K rows ready
        do_qk(b, qt * BM, kt * BN);
        release_add(&g_flags[128 + b * 16 + qt]);          // cntQK
    } else if (bid < 2080) {
        const int v = bid - 1568;
        const int mt = v >> 3, nt = v & 7;
        do_proj(2, mt * BM, nt * BN);
        release_add(&g_flags[256 + (mt >> 4) * 8 + nt]);   // cntV
    } else if (bid < 2592) {
        const int s = bid - 2080;
        const int b = s & 3, mblk = 127 - (s >> 2);        // descending
        const int qt = mblk >> 3;
        wait_cnt(&g_flags[128 + b * 16 + qt], qt + 1);
        softmax_role(b, mblk);
        release_add(&g_flags[192 + b * 16 + qt]);          // cntSM
    } else {
        const int s = bid - 2592;
        const int qt = 15 - (s >> 5);                      // heavy first
        const int rem = s & 31, b = rem & 3, nt = rem >> 2;
        wait_cnt(&g_flags[192 + b * 16 + qt], 8);
        wait_cnt(&g_flags[256 + b * 8 + nt], 16);
        do_pv(out, b, qt * BM, nt * BN);
    }
}

// ---------------- pack kernels ----------------------------------------------
__global__ __launch_bounds__(256)
void pack_x_kernel(const float* __restrict__ x)
{
    __shared__ float sm[16][260];
    const int mb = blockIdx.x;              // 0..511 (16-row group of 8192)
    const int kc = blockIdx.y;              // 0..3 (256-col chunk)
    const float* src = x + (size_t)mb * 16 * DIM + kc * 256;
    for (int i = threadIdx.x; i < 1024; i += 256) {   // 16x256 floats as float4
        int row = i >> 6, c4 = i & 63;
        float4 v = *reinterpret_cast<const float4*>(src + (size_t)row * DIM + c4 * 4);
        *reinterpret_cast<float4*>(&sm[row][c4 * 4]) = v;
    }
    __syncthreads();
    #pragma unroll
    for (int j = 0; j < 4; j++) {
        int s = threadIdx.x + j * 256;      // 0..1023 = 32 kblk x 32 lanes
        int kbl = s >> 5, L = s & 31;
        int r8 = L >> 2, c4 = L & 3;
        float4 v;
        v.x = rna_tf32(sm[r8    ][kbl * 8 + c4    ]);
        v.y = rna_tf32(sm[r8 + 8][kbl * 8 + c4    ]);
        v.z = rna_tf32(sm[r8    ][kbl * 8 + c4 + 4]);
        v.w = rna_tf32(sm[r8 + 8][kbl * 8 + c4 + 4]);
        *reinterpret_cast<float4*>(
            g_PAX + ((size_t)(mb * 128 + kc * 32 + kbl)) * 128 + L * 4) = v;
    }
}

__global__ __launch_bounds__(256)
void pack_w_kernel(const float* __restrict__ Wq,
                   const float* __restrict__ Wk,
                   const float* __restrict__ Wv)
{
    // blocks 0-1 zero the stage flags (replayed every graph iteration)
    if (blockIdx.x < 2) {
        int i = blockIdx.x * 256 + threadIdx.x;
        if (i < 288) g_flags[i] = 0;
    }

    int s = blockIdx.x * 256 + threadIdx.x;
    int L = s & 31, kblk = (s >> 5) & 127, nblk = (s >> 12) & 127, z = s >> 19;
    const float* W = (z == 0) ? Wq : (z == 1) ? Wk : Wv;
    int n = nblk * 8 + (L >> 2), k = kblk * 8 + (L & 3);
    float2 v;
    v.x = rna_tf32(W[(size_t)k * DIM + n]);
    v.y = rna_tf32(W[(size_t)(k + 4) * DIM + n]);
    *reinterpret_cast<float2*>(
        g_PBW + ((size_t)((z * 128 + nblk) * 128 + kblk)) * 64 + L * 2) = v;
}

// ---------------- host side --------------------------------------------------
extern "C" void kernel_launch(void* const* d_in, const int* in_sizes, int n_in,
                              void* d_out, int out_size)
{
    const float* x  = (const float*)d_in[0];
    const float* Wq = (const float*)d_in[1];
    const float* Wk = (const float*)d_in[2];
    const float* Wv = (const float*)d_in[3];
    float* out = (float*)d_out;

    static bool configured = false;
    if (!configured) {
        cudaFuncSetAttribute(mega_kernel, cudaFuncAttributeMaxDynamicSharedMemorySize, SMEM_BYTES);
        configured = true;
    }

    pack_x_kernel<<<dim3(512, 4), 256>>>(x);
    pack_w_kernel<<<6144, 256>>>(Wq, Wk, Wv);
    mega_kernel<<<3104, 128, SMEM_BYTES>>>(out);
}